// round 9
// baseline (speedup 1.0000x reference)
#include <cuda_runtime.h>
#include <cstdint>
#include <cstddef>

#define BZ   256
#define SEQ  512
#define INS  256
#define HID  256

// ---------------------------------------------------------------------------
// helpers
// ---------------------------------------------------------------------------
__device__ __forceinline__ void ffma2(unsigned long long &acc,
                                      unsigned long long a,
                                      unsigned long long b) {
    asm volatile("fma.rn.f32x2 %0, %1, %2, %0;" : "+l"(acc) : "l"(a), "l"(b));
}
__device__ __forceinline__ unsigned long long pack2(float x, float y) {
    unsigned long long r;
    asm("mov.b64 %0, {%1, %2};" : "=l"(r) : "f"(x), "f"(y));
    return r;
}
__device__ __forceinline__ float2 unpack2(unsigned long long v) {
    float2 f;
    asm("mov.b64 {%0, %1}, %2;" : "=f"(f.x), "=f"(f.y) : "l"(v));
    return f;
}
__device__ __forceinline__ float acc_sum(unsigned long long v) {
    float2 p = unpack2(v);
    return p.x + p.y;
}
// fast tanh: 1 - 2/(e^{2x}+1)  via ex2.approx + rcp.approx (~1e-7 abs err)
__device__ __forceinline__ float tanh_fast(float x) {
    float e;
    asm("ex2.approx.f32 %0, %1;" : "=f"(e) : "f"(x * 2.8853900817779268f));
    float r;
    asm("rcp.approx.f32 %0, %1;" : "=f"(r) : "f"(e + 1.0f));
    return fmaf(-2.0f, r, 1.0f);
}
__device__ __forceinline__ void bar_named(int id, int nthreads) {
    asm volatile("bar.sync %0, %1;" :: "r"(id), "r"(nthreads) : "memory");
}

// ---------------------------------------------------------------------------
// Kernel 1: XU = X @ U + bias -> decoder region of d_out.
// v7: X tile staged in SMEM PRE-DUPLICATED as f32x2 (u64): FFMA2 a-operands
// come straight from broadcast LDS.64, removing 8 pack2 MOVs + the mov->ffma
// dependency per k per thread.
// ---------------------------------------------------------------------------
__global__ void __launch_bounds__(256, 2) xu_kernel(
    const float* __restrict__ X, const float* __restrict__ U,
    const float* __restrict__ bias, float* __restrict__ C)
{
    __shared__ unsigned long long Xs[2][16][128];   // (x,x) duplicated pairs
    __shared__ float Us[2][16][128];

    const int tid    = threadIdx.x;
    const int m_base = blockIdx.x * 128;
    const int n_base = blockIdx.y * 128;
    const int tx = tid & 15;
    const int ty = tid >> 4;
    const int m0 = ty * 8;
    const int n0 = tx * 8;

    const int lmx = tid >> 1;
    const int lkx = (tid & 1) * 8;
    const int lku = tid >> 4;
    const int lnu = (tid & 15) * 8;

    const float* Xg = X + (size_t)(m_base + lmx) * 256 + lkx;
    const float* Ug = U + (size_t)lku * 256 + n_base + lnu;

    float4 xa = *(const float4*)(Xg + 0);
    float4 xb = *(const float4*)(Xg + 4);
    float4 ua = *(const float4*)(Ug + 0);
    float4 ub = *(const float4*)(Ug + 4);

    int buf = 0;
    Xs[0][lkx + 0][lmx] = pack2(xa.x, xa.x);
    Xs[0][lkx + 1][lmx] = pack2(xa.y, xa.y);
    Xs[0][lkx + 2][lmx] = pack2(xa.z, xa.z);
    Xs[0][lkx + 3][lmx] = pack2(xa.w, xa.w);
    Xs[0][lkx + 4][lmx] = pack2(xb.x, xb.x);
    Xs[0][lkx + 5][lmx] = pack2(xb.y, xb.y);
    Xs[0][lkx + 6][lmx] = pack2(xb.z, xb.z);
    Xs[0][lkx + 7][lmx] = pack2(xb.w, xb.w);
    *(float4*)&Us[0][lku][lnu]     = ua;
    *(float4*)&Us[0][lku][lnu + 4] = ub;
    __syncthreads();

    unsigned long long acc[8][4];
#pragma unroll
    for (int i = 0; i < 8; i++)
#pragma unroll
        for (int j = 0; j < 4; j++) acc[i][j] = 0ULL;

    for (int kt = 0; kt < 16; kt++) {
        if (kt < 15) {
            const float* Xg2 = Xg + (kt + 1) * 16;
            const float* Ug2 = Ug + (size_t)(kt + 1) * 16 * 256;
            xa = *(const float4*)(Xg2 + 0);
            xb = *(const float4*)(Xg2 + 4);
            ua = *(const float4*)(Ug2 + 0);
            ub = *(const float4*)(Ug2 + 4);
        }
#pragma unroll
        for (int k = 0; k < 16; k++) {
            ulonglong2 bq0 = *(const ulonglong2*)&Us[buf][k][n0];
            ulonglong2 bq1 = *(const ulonglong2*)&Us[buf][k][n0 + 4];
            unsigned long long bb[4] = {bq0.x, bq0.y, bq1.x, bq1.y};
#pragma unroll
            for (int i = 0; i < 8; i++) {
                unsigned long long a2 = Xs[buf][k][m0 + i];  // LDS.64 bcast
                ffma2(acc[i][0], a2, bb[0]);
                ffma2(acc[i][1], a2, bb[1]);
                ffma2(acc[i][2], a2, bb[2]);
                ffma2(acc[i][3], a2, bb[3]);
            }
        }
        if (kt < 15) {
            int nb = buf ^ 1;
            Xs[nb][lkx + 0][lmx] = pack2(xa.x, xa.x);
            Xs[nb][lkx + 1][lmx] = pack2(xa.y, xa.y);
            Xs[nb][lkx + 2][lmx] = pack2(xa.z, xa.z);
            Xs[nb][lkx + 3][lmx] = pack2(xa.w, xa.w);
            Xs[nb][lkx + 4][lmx] = pack2(xb.x, xb.x);
            Xs[nb][lkx + 5][lmx] = pack2(xb.y, xb.y);
            Xs[nb][lkx + 6][lmx] = pack2(xb.z, xb.z);
            Xs[nb][lkx + 7][lmx] = pack2(xb.w, xb.w);
            *(float4*)&Us[nb][lku][lnu]     = ua;
            *(float4*)&Us[nb][lku][lnu + 4] = ub;
            __syncthreads();
            buf = nb;
        }
    }

    float b8[8];
    *(float4*)&b8[0] = *(const float4*)(bias + n_base + n0);
    *(float4*)&b8[4] = *(const float4*)(bias + n_base + n0 + 4);
#pragma unroll
    for (int i = 0; i < 8; i++) {
        float* Cr = C + (size_t)(m_base + m0 + i) * 256 + n_base + n0;
#pragma unroll
        for (int j = 0; j < 4; j++) {
            float2 p = unpack2(acc[i][j]);
            p.x += b8[2 * j];
            p.y += b8[2 * j + 1];
            *(float2*)(Cr + 2 * j) = p;
        }
    }
}

// ---------------------------------------------------------------------------
// Kernel 2 (v7): 128 CTAs x 512 thr, 2 rows/CTA, V in regs (KREG=20) + SMEM
// (KSM=12, 96KB). Changes vs R6:
//  - red DOUBLE-BUFFERED: bar#2's red-reuse guard becomes unnecessary
//    (my reduce-read(t) < my STS(t+1) < full-bar(t+1) < any STS(t+2 same buf)).
//  - bar#2 full __syncthreads -> 2-warp named barrier: h[.][32kw..32kw+32) is
//    produced AND consumed by exactly warps {kw, kw+8}. bar.sync 1+kw, 64.
//  - Part B (smem-V) before Part A (reg-V): LDS latency overlaps reg-FMA.
// ---------------------------------------------------------------------------
#define KREG 20
#define KSM  12
#define VSM_U64S   (8 * (KSM/2) * 256)       // 12288 u64 = 96KB
#define RED_HALF   (8 * 2 * 256)             // 4096 floats = 16KB
#define RED_FLOATS (2 * RED_HALF)            // 32KB
#define HB_FLOATS  (2 * 2 * 256)             // 4KB
#define RNN_SMEM_BYTES (VSM_U64S * 8 + (RED_FLOATS + HB_FLOATS) * 4)

__global__ void __launch_bounds__(512, 1)
rnn_kernel(const float* __restrict__ enc, const float* __restrict__ V,
           float* __restrict__ dec)
{
    extern __shared__ __align__(16) unsigned long long smem_u64[];
    unsigned long long* Vsm = smem_u64;                  // [8][KSM/2][256]
    float* red = (float*)(smem_u64 + VSM_U64S);          // [2][8][2][256]
    float* hb  = red + RED_FLOATS;                       // [2][2][256]

    const int tid = threadIdx.x;
    const int l   = tid & 31;
    const int w   = tid >> 5;
    const int kw  = w & 7;
    const int cw  = w >> 3;
    const int b0  = blockIdx.x * 2;
    const int K   = kw * 32;
    const int col = cw * 128 + l;

    unsigned long long Vr[4][KREG / 2];
#pragma unroll
    for (int cc = 0; cc < 4; cc++) {
        const float* Vc = V + (size_t)K * HID + col + 32 * cc;
#pragma unroll
        for (int j = 0; j < KREG / 2; j++)
            Vr[cc][j] = pack2(Vc[(size_t)(2 * j) * HID],
                              Vc[(size_t)(2 * j + 1) * HID]);
    }
    for (int idx = tid; idx < VSM_U64S; idx += 512) {
        int kk  = idx >> 8;
        int c   = idx & 255;
        int kw2 = kk / (KSM / 2);
        int j   = kk % (KSM / 2);
        int k   = kw2 * 32 + KREG + 2 * j;
        Vsm[idx] = pack2(V[(size_t)k * HID + c], V[(size_t)(k + 1) * HID + c]);
    }
    hb[tid] = enc[(size_t)b0 * HID + tid];
    __syncthreads();

    // finalizer: warp w -> row fr = w>>3, col fc = (w&7)*32 + l  (== tid&255)
    const int fr = tid >> 8;
    const int fc = tid & 255;
    const size_t oBase = ((size_t)(b0 + fr) * SEQ) * HID + fc;

    const int rstore = kw * 512 + cw * 128 + l;   // + r*256 + 32*cc
    const int barid  = 1 + kw;
    int cur = 0;

#pragma unroll 1
    for (int t = 0; t < SEQ; t++) {
        const float xu = dec[oBase + (size_t)t * HID];

        float* redb = red + (t & 1) * RED_HALF;
        const float* h0p = hb + cur * 512 + K;
        const float* h1p = h0p + 256;

        unsigned long long acc[2][4];
#pragma unroll
        for (int r = 0; r < 2; r++)
#pragma unroll
            for (int cc = 0; cc < 4; cc++) acc[r][cc] = 0ULL;

        // ---- Part B first: SMEM V (long-scoreboard loads early)
        const unsigned long long* vsb = Vsm + kw * ((KSM / 2) * 256) + col;
#pragma unroll
        for (int i = 0; i < KSM / 4; i++) {
            ulonglong2 h0 = *(const ulonglong2*)(h0p + KREG + 4 * i);
            ulonglong2 h1 = *(const ulonglong2*)(h1p + KREG + 4 * i);
#pragma unroll
            for (int cc = 0; cc < 4; cc++) {
                unsigned long long v0 = vsb[(2 * i) * 256 + 32 * cc];
                unsigned long long v1 = vsb[(2 * i + 1) * 256 + 32 * cc];
                ffma2(acc[0][cc], h0.x, v0);
                ffma2(acc[0][cc], h0.y, v1);
                ffma2(acc[1][cc], h1.x, v0);
                ffma2(acc[1][cc], h1.y, v1);
            }
        }
        // ---- Part A: register V
#pragma unroll
        for (int i = 0; i < KREG / 4; i++) {
            ulonglong2 h0 = *(const ulonglong2*)(h0p + 4 * i);
            ulonglong2 h1 = *(const ulonglong2*)(h1p + 4 * i);
#pragma unroll
            for (int cc = 0; cc < 4; cc++) {
                ffma2(acc[0][cc], h0.x, Vr[cc][2 * i]);
                ffma2(acc[0][cc], h0.y, Vr[cc][2 * i + 1]);
                ffma2(acc[1][cc], h1.x, Vr[cc][2 * i]);
                ffma2(acc[1][cc], h1.y, Vr[cc][2 * i + 1]);
            }
        }

        // ---- stage partials: red[t&1][kw][r][cw*128 + 32cc + l]
#pragma unroll
        for (int r = 0; r < 2; r++)
#pragma unroll
            for (int cc = 0; cc < 4; cc++)
                redb[rstore + r * 256 + 32 * cc] = acc_sum(acc[r][cc]);
        __syncthreads();                      // bar#1 (full)

        // ---- finalize: 8-way reduce over kw', tanh, store
        float s = 0.f;
#pragma unroll
        for (int ww = 0; ww < 8; ww++)
            s += redb[ww * 512 + fr * 256 + fc];
        const float v = tanh_fast(s + xu);

        dec[oBase + (size_t)t * HID] = v;

        const int nxt = cur ^ 1;
        hb[nxt * 512 + fr * 256 + fc] = v;
        bar_named(barid, 64);                 // pair {kw, kw+8}: h[nxt] ready
        cur = nxt;
    }
}

// ---------------------------------------------------------------------------
// launch
// ---------------------------------------------------------------------------
extern "C" void kernel_launch(void* const* d_in, const int* in_sizes, int n_in,
                              void* d_out, int out_size)
{
    const float* enc  = (const float*)d_in[0];
    const float* xdec = (const float*)d_in[1];
    const float* U    = (const float*)d_in[2];
    const float* V    = (const float*)d_in[3];
    const float* b    = (const float*)d_in[4];

    float* out = (float*)d_out;
    float* dec = out + (size_t)BZ * HID;

    cudaMemcpyAsync(out, enc, (size_t)BZ * HID * sizeof(float),
                    cudaMemcpyDeviceToDevice, 0);

    xu_kernel<<<dim3((BZ * SEQ) / 128, HID / 128), 256>>>(xdec, U, b, dec);

    cudaFuncSetAttribute(rnn_kernel,
                         cudaFuncAttributeMaxDynamicSharedMemorySize,
                         RNN_SMEM_BYTES);
    rnn_kernel<<<128, 512, RNN_SMEM_BYTES>>>(enc, V, dec);
}